// round 11
// baseline (speedup 1.0000x reference)
#include <cuda_runtime.h>
#include <cuda_fp16.h>
#include <cstdint>

#define THREADS     512
#define FDIM        256
#define N_GEMM      24          // z1 = tanh(c), then 24 GEMM iterations (25 total)
#define N_PAIRS     1024        // 32768 rows / 32 rows per tile-pair
#define KREG        9           // k-steps of B held in registers (of 16)

#define ROW_BYTES   512                          // 256 halfs per row
#define W_BYTES     (FDIM * ROW_BYTES)           // 131072
#define ZT_BYTES    (16 * ROW_BYTES)             // 8192 per 16-row z buffer
#define OFF_Z       W_BYTES                      // 4 buffers: [group][buf]
#define SMEM_BYTES  (W_BYTES + 4 * ZT_BYTES)     // 163840 (160 KB)

static __device__ __forceinline__ uint32_t smem_u32(const void* p) {
    uint32_t a;
    asm("{ .reg .u64 t; cvta.to.shared.u64 t, %1; cvt.u32.u64 %0, t; }" : "=r"(a) : "l"(p));
    return a;
}

// Byte offset of half element (r, k) in a swizzled [rows x 256] fp16 tile.
static __device__ __forceinline__ uint32_t swz(uint32_t r, uint32_t k) {
    return r * ROW_BYTES + (((k >> 3) ^ (r & 7)) << 4) + ((k & 7) << 1);
}

static __device__ __forceinline__ void ldsm4(uint32_t r[4], uint32_t addr) {
    asm volatile("ldmatrix.sync.aligned.m8n8.x4.shared.b16 {%0,%1,%2,%3}, [%4];"
                 : "=r"(r[0]), "=r"(r[1]), "=r"(r[2]), "=r"(r[3]) : "r"(addr));
}

static __device__ __forceinline__ void mma16816(float d[4], const uint32_t a[4],
                                                uint32_t b0, uint32_t b1) {
    asm volatile("mma.sync.aligned.m16n8k16.row.col.f32.f16.f16.f32 "
                 "{%0,%1,%2,%3}, {%4,%5,%6,%7}, {%8,%9}, {%0,%1,%2,%3};"
                 : "+f"(d[0]), "+f"(d[1]), "+f"(d[2]), "+f"(d[3])
                 : "r"(a[0]), "r"(a[1]), "r"(a[2]), "r"(a[3]), "r"(b0), "r"(b1));
}

// Packed fp16x2 tanh: one MUFU per value-pair (interior iterations only).
static __device__ __forceinline__ uint32_t tanh_h2(uint32_t h2) {
    uint32_t y;
    asm("tanh.approx.f16x2 %0, %1;" : "=r"(y) : "r"(h2));
    return y;
}

// Accurate final-iteration tanh: 1 - 2/(1 + e^{2x}), ~1e-6 rel error.
static __device__ __forceinline__ float tanh_acc(float x) {
    float e, r;
    asm("ex2.approx.f32 %0, %1;" : "=f"(e) : "f"(x * 2.8853900817779268f));
    asm("rcp.approx.f32 %0, %1;" : "=f"(r) : "f"(1.0f + e));
    return 1.0f - 2.0f * r;
}

// Named barrier: scope = one 8-warp tile-group (256 threads).
static __device__ __forceinline__ void bar_group(int id) {
    asm volatile("bar.sync %0, 256;" :: "r"(id) : "memory");
}

__global__ void __launch_bounds__(THREADS, 1)
fixed_point_kernel(const float* __restrict__ x, const float* __restrict__ W,
                   const float* __restrict__ b, float* __restrict__ out)
{
    extern __shared__ char smem[];
    const uint32_t sb = smem_u32(smem);
    const uint32_t Wb = sb;

    const int tid   = threadIdx.x;
    const int wid   = tid >> 5;
    const int l     = tid & 31;
    const int group = wid >> 3;               // 0: rows [p*32, p*32+16); 1: next 16
    const int wg    = wid & 7;
    const int wn    = wg << 5;                // this warp's 32-col slice of N=256
    const int qr    = l >> 2;
    const int qc    = (l & 3) << 1;
    const int barid = group + 1;

    // ---- One-time: W -> SMEM fp16 swizzled [n][k] (full CTA) ----
    for (int idx = tid; idx < FDIM * (FDIM / 4); idx += THREADS) {
        int n  = idx >> 6;
        int k4 = (idx & 63) << 2;
        float4 wv = *reinterpret_cast<const float4*>(W + n * FDIM + k4);
        __half2 h0 = __floats2half2_rn(wv.x, wv.y);
        __half2 h1 = __floats2half2_rn(wv.z, wv.w);
        uint2 v;
        v.x = *reinterpret_cast<uint32_t*>(&h0);
        v.y = *reinterpret_cast<uint32_t*>(&h1);
        *reinterpret_cast<uint2*>(smem + swz(n, k4)) = v;
    }
    __syncthreads();   // only full-CTA barrier; groups are independent after this

    // ---- One-time: first KREG k-steps of B (n32 slice) -> 72 registers ----
    const uint32_t b_r = (uint32_t)(wn + ((l >> 4) & 1) * 8 + (l & 7));
    const uint32_t b_k = (uint32_t)(((l >> 3) & 1) * 8);
    uint32_t Breg[KREG * 8];
#pragma unroll
    for (int ks = 0; ks < KREG; ++ks) {
        ldsm4(&Breg[ks * 8],     Wb + swz(b_r,      ks * 16 + b_k));
        ldsm4(&Breg[ks * 8 + 4], Wb + swz(b_r + 16, ks * 16 + b_k));
    }

    const uint32_t a_r = (uint32_t)(((l >> 3) & 1) * 8 + (l & 7));
    const uint32_t a_k = (uint32_t)(((l >> 4) & 1) * 8);
    const uint32_t zoff0 = OFF_Z + (uint32_t)group * (2 * ZT_BYTES);  // ping
    const uint32_t zoff1 = zoff0 + ZT_BYTES;                          // pong
    const uint32_t Z0 = sb + zoff0, Z1 = sb + zoff1;

    // ---- Persistent loop over 32-row pairs (each group owns its 16-row half) ----
    for (int pair = blockIdx.x; pair < N_PAIRS; pair += gridDim.x) {
        const int row0 = pair * 32 + group * 16;

        // c = x + b as packed half2: c2[nf*2 + rowhalf]
        uint32_t c2[8];
#pragma unroll
        for (int h = 0; h < 2; ++h) {
            const float* xr = x + (size_t)(row0 + qr + h * 8) * FDIM;
#pragma unroll
            for (int nf = 0; nf < 4; ++nf) {
                int c0 = wn + nf * 8 + qc;
                float2 xv = *reinterpret_cast<const float2*>(xr + c0);
                float2 bv = *reinterpret_cast<const float2*>(b + c0);
                __half2 hc = __floats2half2_rn(xv.x + bv.x, xv.y + bv.y);
                c2[nf * 2 + h] = *reinterpret_cast<uint32_t*>(&hc);
            }
        }

        // Iteration 0: z1 = tanh(c) -> ping buffer
#pragma unroll
        for (int nf = 0; nf < 4; ++nf) {
            int c0 = wn + nf * 8 + qc;
            *reinterpret_cast<uint32_t*>(smem + zoff0 + swz(qr,     c0)) = tanh_h2(c2[nf * 2 + 0]);
            *reinterpret_cast<uint32_t*>(smem + zoff0 + swz(qr + 8, c0)) = tanh_h2(c2[nf * 2 + 1]);
        }
        bar_group(barid);   // also serves as the pair-boundary guard

        float acc[4][4];
#pragma unroll 1
        for (int it = 1; it < N_GEMM; ++it) {
            const uint32_t src  = (it & 1) ? Z0 : Z1;
            const uint32_t dsto = (it & 1) ? zoff1 : zoff0;

#pragma unroll
            for (int nf = 0; nf < 4; ++nf)
#pragma unroll
                for (int h = 0; h < 2; ++h) {
                    __half2 hc = *reinterpret_cast<__half2*>(&c2[nf * 2 + h]);
                    float2 cf = __half22float2(hc);
                    acc[nf][h * 2 + 0] = cf.x;
                    acc[nf][h * 2 + 1] = cf.y;
                }

#pragma unroll
            for (int ks = 0; ks < 16; ++ks) {
                uint32_t a[4];
                ldsm4(a, src + swz(a_r, ks * 16 + a_k));
                uint32_t Bl[8];
                const uint32_t* Bk;
                if (ks < KREG) {
                    Bk = &Breg[ks * 8];
                } else {            // reload tail k-steps of B from (read-only) W smem
                    ldsm4(Bl,     Wb + swz(b_r,      ks * 16 + b_k));
                    ldsm4(Bl + 4, Wb + swz(b_r + 16, ks * 16 + b_k));
                    Bk = Bl;
                }
                mma16816(acc[0], a, Bk[0], Bk[1]);
                mma16816(acc[1], a, Bk[2], Bk[3]);
                mma16816(acc[2], a, Bk[4], Bk[5]);
                mma16816(acc[3], a, Bk[6], Bk[7]);
            }

#pragma unroll
            for (int nf = 0; nf < 4; ++nf) {
                int c0 = wn + nf * 8 + qc;
                __half2 h0 = __floats2half2_rn(acc[nf][0], acc[nf][1]);
                __half2 h1 = __floats2half2_rn(acc[nf][2], acc[nf][3]);
                *reinterpret_cast<uint32_t*>(smem + dsto + swz(qr,     c0)) =
                    tanh_h2(*reinterpret_cast<uint32_t*>(&h0));
                *reinterpret_cast<uint32_t*>(smem + dsto + swz(qr + 8, c0)) =
                    tanh_h2(*reinterpret_cast<uint32_t*>(&h1));
            }
            bar_group(barid);
        }

        // ---- Final iteration (it = 24, reads pong buffer Z1): accurate tanh -> gmem ----
#pragma unroll
        for (int nf = 0; nf < 4; ++nf)
#pragma unroll
            for (int h = 0; h < 2; ++h) {
                __half2 hc = *reinterpret_cast<__half2*>(&c2[nf * 2 + h]);
                float2 cf = __half22float2(hc);
                acc[nf][h * 2 + 0] = cf.x;
                acc[nf][h * 2 + 1] = cf.y;
            }
#pragma unroll
        for (int ks = 0; ks < 16; ++ks) {
            uint32_t a[4];
            ldsm4(a, Z1 + swz(a_r, ks * 16 + a_k));
            uint32_t Bl[8];
            const uint32_t* Bk;
            if (ks < KREG) {
                Bk = &Breg[ks * 8];
            } else {
                ldsm4(Bl,     Wb + swz(b_r,      ks * 16 + b_k));
                ldsm4(Bl + 4, Wb + swz(b_r + 16, ks * 16 + b_k));
                Bk = Bl;
            }
            mma16816(acc[0], a, Bk[0], Bk[1]);
            mma16816(acc[1], a, Bk[2], Bk[3]);
            mma16816(acc[2], a, Bk[4], Bk[5]);
            mma16816(acc[3], a, Bk[6], Bk[7]);
        }
#pragma unroll
        for (int nf = 0; nf < 4; ++nf) {
            int rg = row0 + qr;
            int c0 = wn + nf * 8 + qc;
            float2 v0 = make_float2(tanh_acc(acc[nf][0]), tanh_acc(acc[nf][1]));
            float2 v1 = make_float2(tanh_acc(acc[nf][2]), tanh_acc(acc[nf][3]));
            *reinterpret_cast<float2*>(out + (size_t)rg * FDIM + c0)       = v0;
            *reinterpret_cast<float2*>(out + (size_t)(rg + 8) * FDIM + c0) = v1;
        }
        // No barrier here: final GEMM read Z1; the next pair's iteration 0 writes
        // Z0 and its bar_group gates any Z1 overwrite (it=1 writes zoff1 only
        // after all group warps passed the it0 barrier, i.e. finished this pair).
    }
}

extern "C" void kernel_launch(void* const* d_in, const int* in_sizes, int n_in,
                              void* d_out, int out_size)
{
    (void)in_sizes; (void)n_in; (void)out_size;
    const float* x = (const float*)d_in[0];
    const float* W = (const float*)d_in[1];
    const float* b = (const float*)d_in[2];
    float* out = (float*)d_out;

    int dev = 0, sms = 0;
    cudaGetDevice(&dev);
    cudaDeviceGetAttribute(&sms, cudaDevAttrMultiProcessorCount, dev);
    int grid = sms > 0 ? sms : 128;
    if (grid > N_PAIRS) grid = N_PAIRS;

    cudaFuncSetAttribute(fixed_point_kernel, cudaFuncAttributeMaxDynamicSharedMemorySize, SMEM_BYTES);
    fixed_point_kernel<<<grid, THREADS, SMEM_BYTES>>>(x, W, b, out);
}

// round 12
// speedup vs baseline: 1.0088x; 1.0088x over previous
#include <cuda_runtime.h>
#include <cuda_fp16.h>
#include <cstdint>

#define THREADS     512
#define FDIM        256
#define N_GEMM      24          // z1 = tanh(c), then 24 GEMM iterations (25 total)
#define N_PAIRS     1024        // 32768 rows / 32 rows per tile-pair
#define KHALF       8           // k-steps (of 16) per warp: split-K by 2

#define ROW_BYTES   512                          // 256 halfs per row
#define W_BYTES     (FDIM * ROW_BYTES)           // 131072
#define ZT_BYTES    (16 * ROW_BYTES)             // 8192 per 16-row z buffer
#define OFF_Z       W_BYTES                      // tile t, buf p: OFF_Z + t*16384 + p*8192
#define OFF_P       (OFF_Z + 4 * ZT_BYTES)       // fp32 partial region, 32 KB
#define SMEM_BYTES  (OFF_P + 32768)              // 196608 (192 KB)

static __device__ __forceinline__ uint32_t smem_u32(const void* p) {
    uint32_t a;
    asm("{ .reg .u64 t; cvta.to.shared.u64 t, %1; cvt.u32.u64 %0, t; }" : "=r"(a) : "l"(p));
    return a;
}

// Byte offset of half element (r, k) in a swizzled [rows x 256] fp16 tile.
static __device__ __forceinline__ uint32_t swz(uint32_t r, uint32_t k) {
    return r * ROW_BYTES + (((k >> 3) ^ (r & 7)) << 4) + ((k & 7) << 1);
}

static __device__ __forceinline__ void ldsm4(uint32_t r[4], uint32_t addr) {
    asm volatile("ldmatrix.sync.aligned.m8n8.x4.shared.b16 {%0,%1,%2,%3}, [%4];"
                 : "=r"(r[0]), "=r"(r[1]), "=r"(r[2]), "=r"(r[3]) : "r"(addr));
}

static __device__ __forceinline__ void mma16816(float d[4], const uint32_t a[4],
                                                uint32_t b0, uint32_t b1) {
    asm volatile("mma.sync.aligned.m16n8k16.row.col.f32.f16.f16.f32 "
                 "{%0,%1,%2,%3}, {%4,%5,%6,%7}, {%8,%9}, {%0,%1,%2,%3};"
                 : "+f"(d[0]), "+f"(d[1]), "+f"(d[2]), "+f"(d[3])
                 : "r"(a[0]), "r"(a[1]), "r"(a[2]), "r"(a[3]), "r"(b0), "r"(b1));
}

// Packed fp16x2 tanh: one MUFU per value-pair (interior iterations only).
static __device__ __forceinline__ uint32_t tanh_h2(uint32_t h2) {
    uint32_t y;
    asm("tanh.approx.f16x2 %0, %1;" : "=r"(y) : "r"(h2));
    return y;
}

// Accurate final-iteration tanh: 1 - 2/(1 + e^{2x}), ~1e-6 rel error.
static __device__ __forceinline__ float tanh_acc(float x) {
    float e, r;
    asm("ex2.approx.f32 %0, %1;" : "=f"(e) : "f"(x * 2.8853900817779268f));
    asm("rcp.approx.f32 %0, %1;" : "=f"(r) : "f"(1.0f + e));
    return 1.0f - 2.0f * r;
}

// Pairwise named barrier: the two K-half partner warps of slice s (64 threads).
static __device__ __forceinline__ void bar_pair(int id) {
    asm volatile("bar.sync %0, 64;" :: "r"(id) : "memory");
}

__global__ void __launch_bounds__(THREADS, 1)
fixed_point_kernel(const float* __restrict__ x, const float* __restrict__ W,
                   const float* __restrict__ b, float* __restrict__ out)
{
    extern __shared__ char smem[];
    const uint32_t sb = smem_u32(smem);
    const uint32_t Wb = sb;

    const int tid = threadIdx.x;
    const int wid = tid >> 5;
    const int l   = tid & 31;
    const int s   = wid & 7;                  // n32 slice index
    const int kg  = wid >> 3;                 // K-half (0: k[0,128), 1: k[128,256))
    const int wn  = s << 5;                   // slice's first column
    const int qr  = l >> 2;
    const int qc  = (l & 3) << 1;
    const int kbase = kg * 128;               // element offset of this warp's K-half

    // ---- One-time: W -> SMEM fp16 swizzled [n][k] (full CTA) ----
    for (int idx = tid; idx < FDIM * (FDIM / 4); idx += THREADS) {
        int n  = idx >> 6;
        int k4 = (idx & 63) << 2;
        float4 wv = *reinterpret_cast<const float4*>(W + n * FDIM + k4);
        __half2 h0 = __floats2half2_rn(wv.x, wv.y);
        __half2 h1 = __floats2half2_rn(wv.z, wv.w);
        uint2 v;
        v.x = *reinterpret_cast<uint32_t*>(&h0);
        v.y = *reinterpret_cast<uint32_t*>(&h1);
        *reinterpret_cast<uint2*>(smem + swz(n, k4)) = v;
    }
    __syncthreads();

    // ---- One-time: B fragments (n32 slice, OWN K-half only) -> 64 registers ----
    const uint32_t b_r = (uint32_t)(wn + ((l >> 4) & 1) * 8 + (l & 7));
    const uint32_t b_k = (uint32_t)(((l >> 3) & 1) * 8);
    uint32_t Breg[KHALF * 8];
#pragma unroll
    for (int ks = 0; ks < KHALF; ++ks) {
        ldsm4(&Breg[ks * 8],     Wb + swz(b_r,      kbase + ks * 16 + b_k));
        ldsm4(&Breg[ks * 8 + 4], Wb + swz(b_r + 16, kbase + ks * 16 + b_k));
    }

    const uint32_t a_r = (uint32_t)(((l >> 3) & 1) * 8 + (l & 7));
    const uint32_t a_k = (uint32_t)(((l >> 4) & 1) * 8);
    // Partial-sum addresses (float4 per lane per nf, 512B rows -> conflict-free)
    const uint32_t p_st = OFF_P + (uint32_t)((((1 - kg) * 8 + s) * 4) * 512 + l * 16);
    const uint32_t p_ld = OFF_P + (uint32_t)(((kg * 8 + s) * 4) * 512 + l * 16);
    // z buffer offsets: reduce-tile (kg) for stores; both tiles for GEMM reads
    const uint32_t zmy = OFF_Z + (uint32_t)kg * (2 * ZT_BYTES);

    // ---- Persistent loop over 32-row pairs ----
    for (int pair = blockIdx.x; pair < N_PAIRS; pair += gridDim.x) {
        const int row0 = pair * 32;

        // c = x + b (packed half2) for the tile this warp REDUCES (tile kg), slice s
        uint32_t c2[8];
#pragma unroll
        for (int h = 0; h < 2; ++h) {
            const float* xr = x + (size_t)(row0 + kg * 16 + qr + h * 8) * FDIM;
#pragma unroll
            for (int nf = 0; nf < 4; ++nf) {
                int c0 = wn + nf * 8 + qc;
                float2 xv = *reinterpret_cast<const float2*>(xr + c0);
                float2 bv = *reinterpret_cast<const float2*>(b + c0);
                __half2 hc = __floats2half2_rn(xv.x + bv.x, xv.y + bv.y);
                c2[nf * 2 + h] = *reinterpret_cast<uint32_t*>(&hc);
            }
        }

        // Iteration 0: z1 = tanh(c) -> tile kg, buf 0
#pragma unroll
        for (int nf = 0; nf < 4; ++nf) {
            int c0 = wn + nf * 8 + qc;
            *reinterpret_cast<uint32_t*>(smem + zmy + swz(qr,     c0)) = tanh_h2(c2[nf * 2 + 0]);
            *reinterpret_cast<uint32_t*>(smem + zmy + swz(qr + 8, c0)) = tanh_h2(c2[nf * 2 + 1]);
        }
        __syncthreads();

        float accA[4][4], accB[4][4];
#pragma unroll 1
        for (int it = 1; it <= N_GEMM; ++it) {
            const uint32_t srcp = (uint32_t)((it + 1) & 1);  // buf read this iter
            const uint32_t dstp = (uint32_t)(it & 1);        // buf written this iter
            const uint32_t ZA = sb + OFF_Z + srcp * ZT_BYTES;                  // tile 0
            const uint32_t ZB = sb + OFF_Z + 2 * ZT_BYTES + srcp * ZT_BYTES;   // tile 1

#pragma unroll
            for (int nf = 0; nf < 4; ++nf)
#pragma unroll
                for (int j = 0; j < 4; ++j) {
                    accA[nf][j] = 0.0f;
                    accB[nf][j] = 0.0f;
                }

            // Dual-tile GEMM over OWN K-half: 2 ldsm + 8 independent-acc MMAs / step
#pragma unroll
            for (int ks = 0; ks < KHALF; ++ks) {
                const int k0 = kbase + ks * 16;
                uint32_t aA[4], aB[4];
                ldsm4(aA, ZA + swz(a_r, k0 + a_k));
                ldsm4(aB, ZB + swz(a_r, k0 + a_k));
                const uint32_t* Bk = &Breg[ks * 8];
                mma16816(accA[0], aA, Bk[0], Bk[1]);
                mma16816(accA[1], aA, Bk[2], Bk[3]);
                mma16816(accB[0], aB, Bk[0], Bk[1]);
                mma16816(accB[1], aB, Bk[2], Bk[3]);
                mma16816(accA[2], aA, Bk[4], Bk[5]);
                mma16816(accA[3], aA, Bk[6], Bk[7]);
                mma16816(accB[2], aB, Bk[4], Bk[5]);
                mma16816(accB[3], aB, Bk[6], Bk[7]);
            }

            // Store partial of the OTHER tile (the one our partner reduces)
            {
                const float (*po)[4] = (kg == 0) ? accB : accA;
#pragma unroll
                for (int nf = 0; nf < 4; ++nf)
                    *reinterpret_cast<float4*>(smem + p_st + nf * 512) =
                        make_float4(po[nf][0], po[nf][1], po[nf][2], po[nf][3]);
            }
            bar_pair(s + 1);   // partner's partial now visible

            // Reduce OWN tile: own acc + partner partial + c, activate, store
            {
                const float (*ps)[4] = (kg == 0) ? accA : accB;
                if (it < N_GEMM) {
#pragma unroll
                    for (int nf = 0; nf < 4; ++nf) {
                        float4 p = *reinterpret_cast<const float4*>(smem + p_ld + nf * 512);
                        __half2 hc0 = *reinterpret_cast<__half2*>(&c2[nf * 2 + 0]);
                        __half2 hc1 = *reinterpret_cast<__half2*>(&c2[nf * 2 + 1]);
                        float2 cf0 = __half22float2(hc0);
                        float2 cf1 = __half22float2(hc1);
                        __half2 h0 = __floats2half2_rn(ps[nf][0] + p.x + cf0.x,
                                                       ps[nf][1] + p.y + cf0.y);
                        __half2 h1 = __floats2half2_rn(ps[nf][2] + p.z + cf1.x,
                                                       ps[nf][3] + p.w + cf1.y);
                        int c0 = wn + nf * 8 + qc;
                        *reinterpret_cast<uint32_t*>(smem + zmy + dstp * ZT_BYTES + swz(qr, c0)) =
                            tanh_h2(*reinterpret_cast<uint32_t*>(&h0));
                        *reinterpret_cast<uint32_t*>(smem + zmy + dstp * ZT_BYTES + swz(qr + 8, c0)) =
                            tanh_h2(*reinterpret_cast<uint32_t*>(&h1));
                    }
                    __syncthreads();   // z published to all 16 warps
                } else {
                    // Final iteration: accurate tanh, fp32 straight to gmem
#pragma unroll
                    for (int nf = 0; nf < 4; ++nf) {
                        float4 p = *reinterpret_cast<const float4*>(smem + p_ld + nf * 512);
                        __half2 hc0 = *reinterpret_cast<__half2*>(&c2[nf * 2 + 0]);
                        __half2 hc1 = *reinterpret_cast<__half2*>(&c2[nf * 2 + 1]);
                        float2 cf0 = __half22float2(hc0);
                        float2 cf1 = __half22float2(hc1);
                        int rg = row0 + kg * 16 + qr;
                        int c0 = wn + nf * 8 + qc;
                        float2 v0 = make_float2(tanh_acc(ps[nf][0] + p.x + cf0.x),
                                                tanh_acc(ps[nf][1] + p.y + cf0.y));
                        float2 v1 = make_float2(tanh_acc(ps[nf][2] + p.z + cf1.x),
                                                tanh_acc(ps[nf][3] + p.w + cf1.y));
                        *reinterpret_cast<float2*>(out + (size_t)rg * FDIM + c0)       = v0;
                        *reinterpret_cast<float2*>(out + (size_t)(rg + 8) * FDIM + c0) = v1;
                    }
                    // No barrier: next pair's it0 __syncthreads gates all reuse
                    // (partial region is next written only after that barrier).
                }
            }
        }
    }
}

extern "C" void kernel_launch(void* const* d_in, const int* in_sizes, int n_in,
                              void* d_out, int out_size)
{
    (void)in_sizes; (void)n_in; (void)out_size;
    const float* x = (const float*)d_in[0];
    const float* W = (const float*)d_in[1];
    const float* b = (const float*)d_in[2];
    float* out = (float*)d_out;

    int dev = 0, sms = 0;
    cudaGetDevice(&dev);
    cudaDeviceGetAttribute(&sms, cudaDevAttrMultiProcessorCount, dev);
    int grid = sms > 0 ? sms : 128;
    if (grid > N_PAIRS) grid = N_PAIRS;

    cudaFuncSetAttribute(fixed_point_kernel, cudaFuncAttributeMaxDynamicSharedMemorySize, SMEM_BYTES);
    fixed_point_kernel<<<grid, THREADS, SMEM_BYTES>>>(x, W, b, out);
}

// round 13
// speedup vs baseline: 1.1666x; 1.1564x over previous
#include <cuda_runtime.h>
#include <cuda_fp16.h>
#include <cstdint>

#define THREADS     512
#define FDIM        256
#define N_GEMM      24          // z1 = tanh(c), then 24 GEMM iterations (25 total)
#define N_PAIRS     1024        // 32768 rows / 32 rows per tile-pair

#define ROW_BYTES   512                          // 256 halfs per row
#define W_BYTES     (FDIM * ROW_BYTES)           // 131072
#define ZT_BYTES    (16 * ROW_BYTES)             // 8192 per 16-row z buffer
#define OFF_ZA0     W_BYTES
#define OFF_ZA1     (W_BYTES + ZT_BYTES)
#define OFF_ZB0     (W_BYTES + 2 * ZT_BYTES)
#define OFF_ZB1     (W_BYTES + 3 * ZT_BYTES)
#define SMEM_BYTES  (W_BYTES + 4 * ZT_BYTES)     // 163840 (160 KB)

// Named barrier IDs (1..4), one per z buffer. Count = 1024: 512 producer
// arrives + 512 consumer syncs per use-cycle.
#define BAR_ZA0  1
#define BAR_ZA1  2
#define BAR_ZB0  3
#define BAR_ZB1  4

static __device__ __forceinline__ uint32_t smem_u32(const void* p) {
    uint32_t a;
    asm("{ .reg .u64 t; cvta.to.shared.u64 t, %1; cvt.u32.u64 %0, t; }" : "=r"(a) : "l"(p));
    return a;
}

static __device__ __forceinline__ void bar_arrive(int id) {
    asm volatile("bar.arrive %0, 1024;" :: "r"(id) : "memory");
}
static __device__ __forceinline__ void bar_wait(int id) {
    asm volatile("bar.sync %0, 1024;" :: "r"(id) : "memory");
}

// Byte offset of half element (r, k) in a swizzled [rows x 256] fp16 tile.
static __device__ __forceinline__ uint32_t swz(uint32_t r, uint32_t k) {
    return r * ROW_BYTES + (((k >> 3) ^ (r & 7)) << 4) + ((k & 7) << 1);
}

static __device__ __forceinline__ void ldsm4(uint32_t r[4], uint32_t addr) {
    asm volatile("ldmatrix.sync.aligned.m8n8.x4.shared.b16 {%0,%1,%2,%3}, [%4];"
                 : "=r"(r[0]), "=r"(r[1]), "=r"(r[2]), "=r"(r[3]) : "r"(addr));
}

static __device__ __forceinline__ void mma16816(float d[4], const uint32_t a[4],
                                                uint32_t b0, uint32_t b1) {
    asm volatile("mma.sync.aligned.m16n8k16.row.col.f32.f16.f16.f32 "
                 "{%0,%1,%2,%3}, {%4,%5,%6,%7}, {%8,%9}, {%0,%1,%2,%3};"
                 : "+f"(d[0]), "+f"(d[1]), "+f"(d[2]), "+f"(d[3])
                 : "r"(a[0]), "r"(a[1]), "r"(a[2]), "r"(a[3]), "r"(b0), "r"(b1));
}

// Packed fp16x2 tanh: one MUFU per value-pair (interior iterations only).
static __device__ __forceinline__ uint32_t tanh_h2(uint32_t h2) {
    uint32_t y;
    asm("tanh.approx.f16x2 %0, %1;" : "=r"(y) : "r"(h2));
    return y;
}

// Accurate final-iteration tanh: 1 - 2/(1 + e^{2x}), ~1e-6 rel error.
static __device__ __forceinline__ float tanh_acc(float x) {
    float e, r;
    asm("ex2.approx.f32 %0, %1;" : "=f"(e) : "f"(x * 2.8853900817779268f));
    asm("rcp.approx.f32 %0, %1;" : "=f"(r) : "f"(1.0f + e));
    return 1.0f - 2.0f * r;
}

// Interior epilogue: cvt fp32->half2, packed tanh, STS into z buffer (n16 slice).
static __device__ __forceinline__ void epi_store(
    char* smem, uint32_t zoff, const float v[2][4], int qr, int wn, int qc)
{
#pragma unroll
    for (int nf = 0; nf < 2; ++nf) {
        int c0 = wn + nf * 8 + qc;
        __half2 h0 = __floats2half2_rn(v[nf][0], v[nf][1]);
        __half2 h1 = __floats2half2_rn(v[nf][2], v[nf][3]);
        uint32_t t0 = tanh_h2(*reinterpret_cast<uint32_t*>(&h0));
        uint32_t t1 = tanh_h2(*reinterpret_cast<uint32_t*>(&h1));
        *reinterpret_cast<uint32_t*>(smem + zoff + swz(qr,     c0)) = t0;
        *reinterpret_cast<uint32_t*>(smem + zoff + swz(qr + 8, c0)) = t1;
    }
}

__global__ void __launch_bounds__(THREADS, 1)
fixed_point_kernel(const float* __restrict__ x, const float* __restrict__ W,
                   const float* __restrict__ b, float* __restrict__ out)
{
    extern __shared__ char smem[];
    const uint32_t sb = smem_u32(smem);
    const uint32_t Wb = sb;

    const int tid = threadIdx.x;
    const int wid = tid >> 5;
    const int l   = tid & 31;
    const int wn  = wid << 4;                 // this warp's 16-col slice of N=256
    const int qr  = l >> 2;
    const int qc  = (l & 3) << 1;

    // ---- One-time: W -> SMEM fp16 swizzled [n][k] ----
    for (int idx = tid; idx < FDIM * (FDIM / 4); idx += THREADS) {
        int n  = idx >> 6;
        int k4 = (idx & 63) << 2;
        float4 wv = *reinterpret_cast<const float4*>(W + n * FDIM + k4);
        __half2 h0 = __floats2half2_rn(wv.x, wv.y);
        __half2 h1 = __floats2half2_rn(wv.z, wv.w);
        uint2 v;
        v.x = *reinterpret_cast<uint32_t*>(&h0);
        v.y = *reinterpret_cast<uint32_t*>(&h1);
        *reinterpret_cast<uint2*>(smem + swz(n, k4)) = v;
    }
    __syncthreads();

    // ---- One-time: B fragments (whole K for this warp's n16 slice) -> 64 regs ----
    const uint32_t b_r = (uint32_t)(wn + ((l >> 4) & 1) * 8 + (l & 7));
    const uint32_t b_k = (uint32_t)(((l >> 3) & 1) * 8);
    uint32_t Breg[64];
#pragma unroll
    for (int ks = 0; ks < 16; ++ks)
        ldsm4(&Breg[ks * 4], Wb + swz(b_r, ks * 16 + b_k));

    // ---- One-time: bias values for this thread's output columns ----
    float bias[2][2];
#pragma unroll
    for (int nf = 0; nf < 2; ++nf) {
        float2 bv = *reinterpret_cast<const float2*>(b + wn + nf * 8 + qc);
        bias[nf][0] = bv.x;
        bias[nf][1] = bv.y;
    }

    const uint32_t a_r = (uint32_t)(((l >> 3) & 1) * 8 + (l & 7));
    const uint32_t a_k = (uint32_t)(((l >> 4) & 1) * 8);
    const uint32_t ZA0 = sb + OFF_ZA0, ZA1 = sb + OFF_ZA1;
    const uint32_t ZB0 = sb + OFF_ZB0, ZB1 = sb + OFF_ZB1;

    // ---- Persistent loop over 32-row tile pairs ----
    for (int pair = blockIdx.x; pair < N_PAIRS; pair += gridDim.x) {
        const int row0 = pair * 32;           // tile A rows [row0,row0+16), B next 16

        // c = x + b fragments for both 16-row tiles
        float cA[2][4], cB[2][4];
#pragma unroll
        for (int half = 0; half < 2; ++half) {
            int rA = row0 + qr + half * 8;
            const float* xrA = x + (size_t)rA * FDIM;
            const float* xrB = xrA + 16 * FDIM;
#pragma unroll
            for (int nf = 0; nf < 2; ++nf) {
                int c0 = wn + nf * 8 + qc;
                float2 xa = *reinterpret_cast<const float2*>(xrA + c0);
                float2 xb = *reinterpret_cast<const float2*>(xrB + c0);
                cA[nf][half * 2 + 0] = xa.x + bias[nf][0];
                cA[nf][half * 2 + 1] = xa.y + bias[nf][1];
                cB[nf][half * 2 + 0] = xb.x + bias[nf][0];
                cB[nf][half * 2 + 1] = xb.y + bias[nf][1];
            }
        }

        // Iteration 0: z1 = tanh(c) -> buf 0; signal producers-done via arrive.
        epi_store(smem, OFF_ZA0, cA, qr, wn, qc);
        bar_arrive(BAR_ZA0);
        epi_store(smem, OFF_ZB0, cB, qr, wn, qc);
        bar_arrive(BAR_ZB0);

        // Iterations 1..23: per-buffer producer/consumer barriers.
        // iter it reads buf (it-1)&1, writes buf it&1. The sync on the src
        // barrier also provides WAR safety for the dst buffer (each warp's
        // arrive on buf p follows its read of buf 1-p in program order).
        float acc[2][4];
        uint32_t abuf[2][4];
#pragma unroll 1
        for (int it = 1; it < N_GEMM; ++it) {
            const bool odd = (it & 1) != 0;
            const uint32_t ZAsrc = odd ? ZA0 : ZA1;
            const uint32_t ZBsrc = odd ? ZB0 : ZB1;
            const uint32_t zAdst = odd ? OFF_ZA1 : OFF_ZA0;
            const uint32_t zBdst = odd ? OFF_ZB1 : OFF_ZB0;
            const int barAsrc = odd ? BAR_ZA0 : BAR_ZA1;
            const int barBsrc = odd ? BAR_ZB0 : BAR_ZB1;
            const int barAdst = odd ? BAR_ZA1 : BAR_ZA0;
            const int barBdst = odd ? BAR_ZB1 : BAR_ZB0;

            // ---- tile A: wait src ready, GEMM, epi, signal dst ----
            bar_wait(barAsrc);
#pragma unroll
            for (int nf = 0; nf < 2; ++nf)
#pragma unroll
                for (int j = 0; j < 4; ++j)
                    acc[nf][j] = cA[nf][j];
            ldsm4(abuf[0], ZAsrc + swz(a_r, a_k));
#pragma unroll
            for (int ks = 0; ks < 16; ++ks) {
                if (ks < 15)
                    ldsm4(abuf[(ks + 1) & 1], ZAsrc + swz(a_r, (ks + 1) * 16 + a_k));
                const uint32_t* Bk = &Breg[ks * 4];
                mma16816(acc[0], abuf[ks & 1], Bk[0], Bk[1]);
                mma16816(acc[1], abuf[ks & 1], Bk[2], Bk[3]);
            }
            epi_store(smem, zAdst, acc, qr, wn, qc);
            bar_arrive(barAdst);

            // ---- tile B ----
            bar_wait(barBsrc);
#pragma unroll
            for (int nf = 0; nf < 2; ++nf)
#pragma unroll
                for (int j = 0; j < 4; ++j)
                    acc[nf][j] = cB[nf][j];
            ldsm4(abuf[0], ZBsrc + swz(a_r, a_k));
#pragma unroll
            for (int ks = 0; ks < 16; ++ks) {
                if (ks < 15)
                    ldsm4(abuf[(ks + 1) & 1], ZBsrc + swz(a_r, (ks + 1) * 16 + a_k));
                const uint32_t* Bk = &Breg[ks * 4];
                mma16816(acc[0], abuf[ks & 1], Bk[0], Bk[1]);
                mma16816(acc[1], abuf[ks & 1], Bk[2], Bk[3]);
            }
            epi_store(smem, zBdst, acc, qr, wn, qc);
            bar_arrive(barBdst);
        }

        // ---- Final iteration (it = 24, src buf = 1): sync only, no arrives.
        // All barriers end the pair clean (each reached exactly 1024).
        bar_wait(BAR_ZA1);
#pragma unroll
        for (int nf = 0; nf < 2; ++nf)
#pragma unroll
            for (int j = 0; j < 4; ++j)
                acc[nf][j] = cA[nf][j];
        ldsm4(abuf[0], ZA1 + swz(a_r, a_k));
#pragma unroll
        for (int ks = 0; ks < 16; ++ks) {
            if (ks < 15)
                ldsm4(abuf[(ks + 1) & 1], ZA1 + swz(a_r, (ks + 1) * 16 + a_k));
            const uint32_t* Bk = &Breg[ks * 4];
            mma16816(acc[0], abuf[ks & 1], Bk[0], Bk[1]);
            mma16816(acc[1], abuf[ks & 1], Bk[2], Bk[3]);
        }
#pragma unroll
        for (int nf = 0; nf < 2; ++nf) {
            int rg = row0 + qr;
            int c0 = wn + nf * 8 + qc;
            float2 v0 = make_float2(tanh_acc(acc[nf][0]), tanh_acc(acc[nf][1]));
            float2 v1 = make_float2(tanh_acc(acc[nf][2]), tanh_acc(acc[nf][3]));
            *reinterpret_cast<float2*>(out + (size_t)rg * FDIM + c0)       = v0;
            *reinterpret_cast<float2*>(out + (size_t)(rg + 8) * FDIM + c0) = v1;
        }

        bar_wait(BAR_ZB1);
#pragma unroll
        for (int nf = 0; nf < 2; ++nf)
#pragma unroll
            for (int j = 0; j < 4; ++j)
                acc[nf][j] = cB[nf][j];
        ldsm4(abuf[0], ZB1 + swz(a_r, a_k));
#pragma unroll
        for (int ks = 0; ks < 16; ++ks) {
            if (ks < 15)
                ldsm4(abuf[(ks + 1) & 1], ZB1 + swz(a_r, (ks + 1) * 16 + a_k));
            const uint32_t* Bk = &Breg[ks * 4];
            mma16816(acc[0], abuf[ks & 1], Bk[0], Bk[1]);
            mma16816(acc[1], abuf[ks & 1], Bk[2], Bk[3]);
        }
#pragma unroll
        for (int nf = 0; nf < 2; ++nf) {
            int rg = row0 + 16 + qr;
            int c0 = wn + nf * 8 + qc;
            float2 v0 = make_float2(tanh_acc(acc[nf][0]), tanh_acc(acc[nf][1]));
            float2 v1 = make_float2(tanh_acc(acc[nf][2]), tanh_acc(acc[nf][3]));
            *reinterpret_cast<float2*>(out + (size_t)rg * FDIM + c0)       = v0;
            *reinterpret_cast<float2*>(out + (size_t)(rg + 8) * FDIM + c0) = v1;
        }

        __syncthreads();   // pair boundary (barrier state already clean)
    }
}

extern "C" void kernel_launch(void* const* d_in, const int* in_sizes, int n_in,
                              void* d_out, int out_size)
{
    (void)in_sizes; (void)n_in; (void)out_size;
    const float* x = (const float*)d_in[0];
    const float* W = (const float*)d_in[1];
    const float* b = (const float*)d_in[2];
    float* out = (float*)d_out;

    int dev = 0, sms = 0;
    cudaGetDevice(&dev);
    cudaDeviceGetAttribute(&sms, cudaDevAttrMultiProcessorCount, dev);
    int grid = sms > 0 ? sms : 128;
    if (grid > N_PAIRS) grid = N_PAIRS;

    cudaFuncSetAttribute(fixed_point_kernel, cudaFuncAttributeMaxDynamicSharedMemorySize, SMEM_BYTES);
    fixed_point_kernel<<<grid, THREADS, SMEM_BYTES>>>(x, W, b, out);
}

// round 14
// speedup vs baseline: 1.2847x; 1.1013x over previous
#include <cuda_runtime.h>
#include <cuda_fp16.h>
#include <cstdint>

#define THREADS     512
#define FDIM        256
#define N_GEMM      24          // z1 = tanh(c), then 24 GEMM iterations (25 total)
#define N_PAIRS     1024        // 32768 rows / 32 rows per tile-pair

#define ROW_BYTES   512                          // 256 halfs per row
#define W_BYTES     (FDIM * ROW_BYTES)           // 131072
#define ZT_BYTES    (16 * ROW_BYTES)             // 8192 per 16-row z buffer
#define OFF_ZA0     W_BYTES
#define OFF_ZA1     (W_BYTES + ZT_BYTES)
#define OFF_ZB0     (W_BYTES + 2 * ZT_BYTES)
#define OFF_ZB1     (W_BYTES + 3 * ZT_BYTES)
#define SMEM_BYTES  (W_BYTES + 4 * ZT_BYTES)     // 163840 (160 KB)

static __device__ __forceinline__ uint32_t smem_u32(const void* p) {
    uint32_t a;
    asm("{ .reg .u64 t; cvta.to.shared.u64 t, %1; cvt.u32.u64 %0, t; }" : "=r"(a) : "l"(p));
    return a;
}

// Byte offset of half element (r, k) in a swizzled [rows x 256] fp16 tile.
static __device__ __forceinline__ uint32_t swz(uint32_t r, uint32_t k) {
    return r * ROW_BYTES + (((k >> 3) ^ (r & 7)) << 4) + ((k & 7) << 1);
}

static __device__ __forceinline__ void ldsm4(uint32_t r[4], uint32_t addr) {
    asm volatile("ldmatrix.sync.aligned.m8n8.x4.shared.b16 {%0,%1,%2,%3}, [%4];"
                 : "=r"(r[0]), "=r"(r[1]), "=r"(r[2]), "=r"(r[3]) : "r"(addr));
}

static __device__ __forceinline__ void mma16816(float d[4], const uint32_t a[4],
                                                uint32_t b0, uint32_t b1) {
    asm volatile("mma.sync.aligned.m16n8k16.row.col.f32.f16.f16.f32 "
                 "{%0,%1,%2,%3}, {%4,%5,%6,%7}, {%8,%9}, {%0,%1,%2,%3};"
                 : "+f"(d[0]), "+f"(d[1]), "+f"(d[2]), "+f"(d[3])
                 : "r"(a[0]), "r"(a[1]), "r"(a[2]), "r"(a[3]), "r"(b0), "r"(b1));
}

// Packed fp16x2 tanh: one MUFU per value-pair (interior iterations only).
static __device__ __forceinline__ uint32_t tanh_h2(uint32_t h2) {
    uint32_t y;
    asm("tanh.approx.f16x2 %0, %1;" : "=r"(y) : "r"(h2));
    return y;
}

// Accurate final-iteration tanh: 1 - 2/(1 + e^{2x}), ~1e-6 rel error.
static __device__ __forceinline__ float tanh_acc(float x) {
    float e, r;
    asm("ex2.approx.f32 %0, %1;" : "=f"(e) : "f"(x * 2.8853900817779268f));
    asm("rcp.approx.f32 %0, %1;" : "=f"(r) : "f"(1.0f + e));
    return 1.0f - 2.0f * r;
}

__global__ void __launch_bounds__(THREADS, 1)
fixed_point_kernel(const float* __restrict__ x, const float* __restrict__ W,
                   const float* __restrict__ b, float* __restrict__ out)
{
    extern __shared__ char smem[];
    const uint32_t sb = smem_u32(smem);
    const uint32_t Wb = sb;

    const int tid = threadIdx.x;
    const int wid = tid >> 5;
    const int l   = tid & 31;
    const int wn  = wid << 4;                 // this warp's 16-col slice of N=256
    const int qr  = l >> 2;
    const int qc  = (l & 3) << 1;

    // ---- One-time: W -> SMEM fp16 swizzled [n][k] ----
    for (int idx = tid; idx < FDIM * (FDIM / 4); idx += THREADS) {
        int n  = idx >> 6;
        int k4 = (idx & 63) << 2;
        float4 wv = *reinterpret_cast<const float4*>(W + n * FDIM + k4);
        __half2 h0 = __floats2half2_rn(wv.x, wv.y);
        __half2 h1 = __floats2half2_rn(wv.z, wv.w);
        uint2 v;
        v.x = *reinterpret_cast<uint32_t*>(&h0);
        v.y = *reinterpret_cast<uint32_t*>(&h1);
        *reinterpret_cast<uint2*>(smem + swz(n, k4)) = v;
    }
    __syncthreads();

    // ---- One-time: B fragments (whole K for this warp's n16 slice) -> 64 regs ----
    const uint32_t b_r = (uint32_t)(wn + ((l >> 4) & 1) * 8 + (l & 7));
    const uint32_t b_k = (uint32_t)(((l >> 3) & 1) * 8);
    uint32_t Breg[64];
#pragma unroll
    for (int ks = 0; ks < 16; ++ks)
        ldsm4(&Breg[ks * 4], Wb + swz(b_r, ks * 16 + b_k));

    const uint32_t a_r = (uint32_t)(((l >> 3) & 1) * 8 + (l & 7));
    const uint32_t a_k = (uint32_t)(((l >> 4) & 1) * 8);
    const uint32_t ZA0 = sb + OFF_ZA0, ZA1 = sb + OFF_ZA1;
    const uint32_t ZB0 = sb + OFF_ZB0, ZB1 = sb + OFF_ZB1;

    // ---- Persistent loop over 32-row tile pairs ----
    for (int pair = blockIdx.x; pair < N_PAIRS; pair += gridDim.x) {
        const int row0 = pair * 32;           // tile A rows [row0,row0+16), B next 16

        // c = x + b, packed half2: cA2/cB2[nf*2 + rowhalf]
        uint32_t cA2[4], cB2[4];
#pragma unroll
        for (int h = 0; h < 2; ++h) {
            const float* xrA = x + (size_t)(row0 + qr + h * 8) * FDIM;
            const float* xrB = xrA + 16 * FDIM;
#pragma unroll
            for (int nf = 0; nf < 2; ++nf) {
                int c0 = wn + nf * 8 + qc;
                float2 bv = *reinterpret_cast<const float2*>(b + c0);
                float2 xa = *reinterpret_cast<const float2*>(xrA + c0);
                float2 xb = *reinterpret_cast<const float2*>(xrB + c0);
                __half2 ha = __floats2half2_rn(xa.x + bv.x, xa.y + bv.y);
                __half2 hb = __floats2half2_rn(xb.x + bv.x, xb.y + bv.y);
                cA2[nf * 2 + h] = *reinterpret_cast<uint32_t*>(&ha);
                cB2[nf * 2 + h] = *reinterpret_cast<uint32_t*>(&hb);
            }
        }

        // Iteration 0: z1 = tanh(c) -> buf 0
#pragma unroll
        for (int nf = 0; nf < 2; ++nf) {
            int c0 = wn + nf * 8 + qc;
            *reinterpret_cast<uint32_t*>(smem + OFF_ZA0 + swz(qr,     c0)) = tanh_h2(cA2[nf * 2 + 0]);
            *reinterpret_cast<uint32_t*>(smem + OFF_ZA0 + swz(qr + 8, c0)) = tanh_h2(cA2[nf * 2 + 1]);
            *reinterpret_cast<uint32_t*>(smem + OFF_ZB0 + swz(qr,     c0)) = tanh_h2(cB2[nf * 2 + 0]);
            *reinterpret_cast<uint32_t*>(smem + OFF_ZB0 + swz(qr + 8, c0)) = tanh_h2(cB2[nf * 2 + 1]);
        }
        __syncthreads();

        // Iterations 1..23: interleaved dual-tile GEMM, one barrier per iter.
        float accA[2][4], accB[2][4];
        uint32_t aA[2][4], aB[2][4];
#pragma unroll 1
        for (int it = 1; it < N_GEMM; ++it) {
            const bool odd = (it & 1) != 0;
            const uint32_t ZAsrc = odd ? ZA0 : ZA1;
            const uint32_t ZBsrc = odd ? ZB0 : ZB1;
            const uint32_t zAdst = odd ? OFF_ZA1 : OFF_ZA0;
            const uint32_t zBdst = odd ? OFF_ZB1 : OFF_ZB0;

#pragma unroll
            for (int nf = 0; nf < 2; ++nf)
#pragma unroll
                for (int h = 0; h < 2; ++h) {
                    float2 fa = __half22float2(*reinterpret_cast<__half2*>(&cA2[nf * 2 + h]));
                    float2 fb = __half22float2(*reinterpret_cast<__half2*>(&cB2[nf * 2 + h]));
                    accA[nf][h * 2 + 0] = fa.x; accA[nf][h * 2 + 1] = fa.y;
                    accB[nf][h * 2 + 0] = fb.x; accB[nf][h * 2 + 1] = fb.y;
                }

            // Single ramp: prefetch step 0 for BOTH tiles, then pipeline.
            ldsm4(aA[0], ZAsrc + swz(a_r, a_k));
            ldsm4(aB[0], ZBsrc + swz(a_r, a_k));
#pragma unroll
            for (int ks = 0; ks < 16; ++ks) {
                const int cur = ks & 1, nxt = cur ^ 1;
                if (ks < 15) {
                    ldsm4(aA[nxt], ZAsrc + swz(a_r, (ks + 1) * 16 + a_k));
                    ldsm4(aB[nxt], ZBsrc + swz(a_r, (ks + 1) * 16 + a_k));
                }
                const uint32_t* Bk = &Breg[ks * 4];
                mma16816(accA[0], aA[cur], Bk[0], Bk[1]);
                mma16816(accB[0], aB[cur], Bk[0], Bk[1]);
                mma16816(accA[1], aA[cur], Bk[2], Bk[3]);
                mma16816(accB[1], aB[cur], Bk[2], Bk[3]);
            }

            // Epilogue both tiles, then the single full barrier.
#pragma unroll
            for (int nf = 0; nf < 2; ++nf) {
                int c0 = wn + nf * 8 + qc;
                __half2 a0 = __floats2half2_rn(accA[nf][0], accA[nf][1]);
                __half2 a1 = __floats2half2_rn(accA[nf][2], accA[nf][3]);
                __half2 b0 = __floats2half2_rn(accB[nf][0], accB[nf][1]);
                __half2 b1 = __floats2half2_rn(accB[nf][2], accB[nf][3]);
                *reinterpret_cast<uint32_t*>(smem + zAdst + swz(qr,     c0)) =
                    tanh_h2(*reinterpret_cast<uint32_t*>(&a0));
                *reinterpret_cast<uint32_t*>(smem + zAdst + swz(qr + 8, c0)) =
                    tanh_h2(*reinterpret_cast<uint32_t*>(&a1));
                *reinterpret_cast<uint32_t*>(smem + zBdst + swz(qr,     c0)) =
                    tanh_h2(*reinterpret_cast<uint32_t*>(&b0));
                *reinterpret_cast<uint32_t*>(smem + zBdst + swz(qr + 8, c0)) =
                    tanh_h2(*reinterpret_cast<uint32_t*>(&b1));
            }
            __syncthreads();
        }

        // ---- Final iteration (it = 24, src = buf 1): accurate tanh -> gmem ----
#pragma unroll
        for (int nf = 0; nf < 2; ++nf)
#pragma unroll
            for (int h = 0; h < 2; ++h) {
                float2 fa = __half22float2(*reinterpret_cast<__half2*>(&cA2[nf * 2 + h]));
                float2 fb = __half22float2(*reinterpret_cast<__half2*>(&cB2[nf * 2 + h]));
                accA[nf][h * 2 + 0] = fa.x; accA[nf][h * 2 + 1] = fa.y;
                accB[nf][h * 2 + 0] = fb.x; accB[nf][h * 2 + 1] = fb.y;
            }
        ldsm4(aA[0], ZA1 + swz(a_r, a_k));
        ldsm4(aB[0], ZB1 + swz(a_r, a_k));
#pragma unroll
        for (int ks = 0; ks < 16; ++ks) {
            const int cur = ks & 1, nxt = cur ^ 1;
            if (ks < 15) {
                ldsm4(aA[nxt], ZA1 + swz(a_r, (ks + 1) * 16 + a_k));
                ldsm4(aB[nxt], ZB1 + swz(a_r, (ks + 1) * 16 + a_k));
            }
            const uint32_t* Bk = &Breg[ks * 4];
            mma16816(accA[0], aA[cur], Bk[0], Bk[1]);
            mma16816(accB[0], aB[cur], Bk[0], Bk[1]);
            mma16816(accA[1], aA[cur], Bk[2], Bk[3]);
            mma16816(accB[1], aB[cur], Bk[2], Bk[3]);
        }
#pragma unroll
        for (int nf = 0; nf < 2; ++nf) {
            int c0 = wn + nf * 8 + qc;
            int rgA = row0 + qr;
            int rgB = row0 + 16 + qr;
            float2 vA0 = make_float2(tanh_acc(accA[nf][0]), tanh_acc(accA[nf][1]));
            float2 vA1 = make_float2(tanh_acc(accA[nf][2]), tanh_acc(accA[nf][3]));
            float2 vB0 = make_float2(tanh_acc(accB[nf][0]), tanh_acc(accB[nf][1]));
            float2 vB1 = make_float2(tanh_acc(accB[nf][2]), tanh_acc(accB[nf][3]));
            *reinterpret_cast<float2*>(out + (size_t)rgA * FDIM + c0)       = vA0;
            *reinterpret_cast<float2*>(out + (size_t)(rgA + 8) * FDIM + c0) = vA1;
            *reinterpret_cast<float2*>(out + (size_t)rgB * FDIM + c0)       = vB0;
            *reinterpret_cast<float2*>(out + (size_t)(rgB + 8) * FDIM + c0) = vB1;
        }
        __syncthreads();   // z buffers safe for next pair's iteration 0
    }
}

extern "C" void kernel_launch(void* const* d_in, const int* in_sizes, int n_in,
                              void* d_out, int out_size)
{
    (void)in_sizes; (void)n_in; (void)out_size;
    const float* x = (const float*)d_in[0];
    const float* W = (const float*)d_in[1];
    const float* b = (const float*)d_in[2];
    float* out = (float*)d_out;

    int dev = 0, sms = 0;
    cudaGetDevice(&dev);
    cudaDeviceGetAttribute(&sms, cudaDevAttrMultiProcessorCount, dev);
    int grid = sms > 0 ? sms : 128;
    if (grid > N_PAIRS) grid = N_PAIRS;

    cudaFuncSetAttribute(fixed_point_kernel, cudaFuncAttributeMaxDynamicSharedMemorySize, SMEM_BYTES);
    fixed_point_kernel<<<grid, THREADS, SMEM_BYTES>>>(x, W, b, out);
}